// round 5
// baseline (speedup 1.0000x reference)
#include <cuda_runtime.h>
#include <math.h>

#define N_MAX   32768
#define EMAX    600000
#define FULL_M  0xffffffffu
#define NEG_SLOPE 0.2f
#define EPS_    1e-16f

// ---------------- device scratch (static: no allocation allowed) ----------------
__device__ int   g_counts[N_MAX];
__device__ int   g_cursor[N_MAX];
__device__ int   g_rowptr[N_MAX + 1];
__device__ int   g_csr_src[EMAX];
__device__ __align__(16) float g_h1[N_MAX * 128];
__device__ __align__(16) float g_act1[N_MAX * 128];
__device__ __align__(16) float g_h2[N_MAX * 128];
__device__ float4 g_as1[N_MAX];
__device__ float4 g_ad1[N_MAX];
__device__ float  g_as2[N_MAX];
__device__ float  g_ad2[N_MAX];

__device__ __forceinline__ float lrelu(float v) { return v > 0.f ? v : NEG_SLOPE * v; }

// ---------------- CSR construction ----------------
__global__ void init_kernel(int n) {
    int i = blockIdx.x * blockDim.x + threadIdx.x;
    if (i < n) g_counts[i] = 1;                       // count=1: implicit self loop
}

__global__ void hist_kernel(const int* __restrict__ dst, int E) {
    int i = (blockIdx.x * blockDim.x + threadIdx.x) * 4;
    if (i + 3 < E) {
        int4 d = *(const int4*)(dst + i);
        atomicAdd(&g_counts[d.x], 1);
        atomicAdd(&g_counts[d.y], 1);
        atomicAdd(&g_counts[d.z], 1);
        atomicAdd(&g_counts[d.w], 1);
    } else {
        for (int j = i; j < E; j++) atomicAdd(&g_counts[dst[j]], 1);
    }
}

// single-block scan: 1024 threads x 32 elems. Epilogue writes rowptr, places the
// self loop at slot rowptr[i], and sets cursor = rowptr[i]+1.
__global__ __launch_bounds__(1024) void scan_kernel(int n) {
    __shared__ int wsum[32];
    int tid = threadIdx.x, lane = tid & 31, wid = tid >> 5;
    int base = tid * 32;
    int local[32];
    int sum = 0;
    #pragma unroll
    for (int j = 0; j < 32; j++) {
        int i = base + j;
        local[j] = sum;
        sum += (i < n) ? g_counts[i] : 0;
    }
    int x = sum;
    #pragma unroll
    for (int d = 1; d < 32; d <<= 1) {
        int t = __shfl_up_sync(FULL_M, x, d);
        if (lane >= d) x += t;
    }
    if (lane == 31) wsum[wid] = x;
    __syncthreads();
    if (wid == 0) {
        int y = wsum[lane];
        #pragma unroll
        for (int d = 1; d < 32; d <<= 1) {
            int t = __shfl_up_sync(FULL_M, y, d);
            if (lane >= d) y += t;
        }
        wsum[lane] = y;
    }
    __syncthreads();
    int offset = (x - sum) + (wid > 0 ? wsum[wid - 1] : 0);
    if (tid == 0) g_rowptr[0] = 0;
    #pragma unroll
    for (int j = 0; j < 32; j++) {
        int i = base + j;
        if (i < n) {
            int c = g_counts[i];
            int start = offset + local[j];
            g_rowptr[i + 1] = start + c;
            g_cursor[i] = start + 1;
            g_csr_src[start] = i;                     // self loop first
        }
    }
}

__global__ void scatter_kernel(const int* __restrict__ src,
                               const int* __restrict__ dst, int E) {
    int i = (blockIdx.x * blockDim.x + threadIdx.x) * 4;
    if (i + 3 < E) {
        int4 s = *(const int4*)(src + i);
        int4 d = *(const int4*)(dst + i);
        int p0 = atomicAdd(&g_cursor[d.x], 1);
        int p1 = atomicAdd(&g_cursor[d.y], 1);
        int p2 = atomicAdd(&g_cursor[d.z], 1);
        int p3 = atomicAdd(&g_cursor[d.w], 1);
        g_csr_src[p0] = s.x; g_csr_src[p1] = s.y;
        g_csr_src[p2] = s.z; g_csr_src[p3] = s.w;
    } else {
        for (int j = i; j < E; j++) {
            int p = atomicAdd(&g_cursor[dst[j]], 1);
            g_csr_src[p] = src[j];
        }
    }
}

// ---------------- GEMM: C[M,128] = A[M,128] * B[128,128], 128x128 tile, 8x8 micro ----------------
__global__ __launch_bounds__(256) void gemm128(const float* __restrict__ A,
                                               const float* __restrict__ B,
                                               float* __restrict__ C, int M) {
    __shared__ __align__(16) float As[16][132];   // [k][m]
    __shared__ __align__(16) float Bs[16][132];   // [k][n]
    int tid = threadIdx.x;
    int tx = tid & 15, ty = tid >> 4;
    int m0 = blockIdx.x * 128;
    float acc[8][8] = {};
    for (int kp = 0; kp < 8; kp++) {
        int k0 = kp * 16;
        #pragma unroll
        for (int j = 0; j < 2; j++) {
            int idx = tid + j * 256;
            int r = idx >> 2, c4 = idx & 3;
            float4 v = make_float4(0.f, 0.f, 0.f, 0.f);
            if (m0 + r < M) v = *(const float4*)(A + (size_t)(m0 + r) * 128 + k0 + c4 * 4);
            As[c4 * 4 + 0][r] = v.x;
            As[c4 * 4 + 1][r] = v.y;
            As[c4 * 4 + 2][r] = v.z;
            As[c4 * 4 + 3][r] = v.w;
        }
        #pragma unroll
        for (int j = 0; j < 2; j++) {
            int idx = tid + j * 256;
            int r = idx >> 5, c4 = idx & 31;
            float4 v = *(const float4*)(B + (k0 + r) * 128 + c4 * 4);
            *(float4*)&Bs[r][c4 * 4] = v;
        }
        __syncthreads();
        #pragma unroll
        for (int k = 0; k < 16; k++) {
            float a[8], b[8];
            *(float4*)&a[0] = *(const float4*)&As[k][ty * 8];
            *(float4*)&a[4] = *(const float4*)&As[k][ty * 8 + 4];
            *(float4*)&b[0] = *(const float4*)&Bs[k][tx * 8];
            *(float4*)&b[4] = *(const float4*)&Bs[k][tx * 8 + 4];
            #pragma unroll
            for (int i = 0; i < 8; i++)
                #pragma unroll
                for (int jj = 0; jj < 8; jj++)
                    acc[i][jj] += a[i] * b[jj];
        }
        __syncthreads();
    }
    #pragma unroll
    for (int i = 0; i < 8; i++) {
        int row = m0 + ty * 8 + i;
        if (row < M) {
            *(float4*)(C + (size_t)row * 128 + tx * 8)     = *(float4*)&acc[i][0];
            *(float4*)(C + (size_t)row * 128 + tx * 8 + 4) = *(float4*)&acc[i][4];
        }
    }
}

// ---------------- per-node attention coefficients ----------------
__global__ void alpha1_kernel(const float* __restrict__ h,
                              const float* __restrict__ a_src,
                              const float* __restrict__ a_dst, int n) {
    int w = (blockIdx.x * blockDim.x + threadIdx.x) >> 5;
    int lane = threadIdx.x & 31;
    if (w >= n) return;
    float4 hv = *(const float4*)(h + (size_t)w * 128 + lane * 4);
    float4 av = *(const float4*)(a_src + lane * 4);
    float4 dv = *(const float4*)(a_dst + lane * 4);
    float ps = hv.x * av.x + hv.y * av.y + hv.z * av.z + hv.w * av.w;
    float pd = hv.x * dv.x + hv.y * dv.y + hv.z * dv.z + hv.w * dv.w;
    #pragma unroll
    for (int o = 4; o; o >>= 1) {        // reduce within 8-lane head groups
        ps += __shfl_xor_sync(FULL_M, ps, o);
        pd += __shfl_xor_sync(FULL_M, pd, o);
    }
    float s0 = __shfl_sync(FULL_M, ps, 0),  s1 = __shfl_sync(FULL_M, ps, 8);
    float s2 = __shfl_sync(FULL_M, ps, 16), s3 = __shfl_sync(FULL_M, ps, 24);
    float d0 = __shfl_sync(FULL_M, pd, 0),  d1 = __shfl_sync(FULL_M, pd, 8);
    float d2 = __shfl_sync(FULL_M, pd, 16), d3 = __shfl_sync(FULL_M, pd, 24);
    if (lane == 0) {
        g_as1[w] = make_float4(s0, s1, s2, s3);
        g_ad1[w] = make_float4(d0, d1, d2, d3);
    }
}

__global__ void alpha2_kernel(const float* __restrict__ h,
                              const float* __restrict__ a_src,
                              const float* __restrict__ a_dst, int n) {
    int w = (blockIdx.x * blockDim.x + threadIdx.x) >> 5;
    int lane = threadIdx.x & 31;
    if (w >= n) return;
    float4 hv = *(const float4*)(h + (size_t)w * 128 + lane * 4);
    float4 av = *(const float4*)(a_src + lane * 4);
    float4 dv = *(const float4*)(a_dst + lane * 4);
    float s = hv.x * av.x + hv.y * av.y + hv.z * av.z + hv.w * av.w;
    float d = hv.x * dv.x + hv.y * dv.y + hv.z * dv.z + hv.w * dv.w;
    #pragma unroll
    for (int o = 16; o; o >>= 1) {
        s += __shfl_xor_sync(FULL_M, s, o);
        d += __shfl_xor_sync(FULL_M, d, o);
    }
    if (lane == 0) { g_as2[w] = s; g_ad2[w] = d; }
}

// ---------------- layer-1 aggregation (4 heads x 32 ch), no max pass, float4 gathers ----------------
__global__ void agg1_kernel(const float* __restrict__ h,
                            const float* __restrict__ b1,
                            float* __restrict__ out, int n) {
    int w = (blockIdx.x * blockDim.x + threadIdx.x) >> 5;
    int lane = threadIdx.x & 31;
    if (w >= n) return;
    int beg = g_rowptr[w], end = g_rowptr[w + 1];
    float4 ad = g_ad1[w];
    int head = lane >> 3;   // channels [4*lane, 4*lane+4) all in head lane>>3

    float4 acc = make_float4(0.f, 0.f, 0.f, 0.f);
    float4 dn4 = make_float4(0.f, 0.f, 0.f, 0.f);
    for (int g = beg; g < end; g += 32) {
        int i = g + lane;
        float4 e4 = make_float4(0.f, 0.f, 0.f, 0.f);
        int s = 0;
        if (i < end) {
            s = g_csr_src[i];
            float4 a = g_as1[s];
            e4.x = __expf(lrelu(a.x + ad.x));
            e4.y = __expf(lrelu(a.y + ad.y));
            e4.z = __expf(lrelu(a.z + ad.z));
            e4.w = __expf(lrelu(a.w + ad.w));
        }
        dn4.x += e4.x; dn4.y += e4.y; dn4.z += e4.z; dn4.w += e4.w;
        int cnt = min(32, end - g);
        for (int j = 0; j < cnt; j++) {
            float f0 = __shfl_sync(FULL_M, e4.x, j);
            float f1 = __shfl_sync(FULL_M, e4.y, j);
            float f2 = __shfl_sync(FULL_M, e4.z, j);
            float f3 = __shfl_sync(FULL_M, e4.w, j);
            int  sj = __shfl_sync(FULL_M, s, j);
            float f = head == 0 ? f0 : (head == 1 ? f1 : (head == 2 ? f2 : f3));
            float4 hv = *(const float4*)(h + (size_t)sj * 128 + lane * 4);
            acc.x += f * hv.x; acc.y += f * hv.y;
            acc.z += f * hv.z; acc.w += f * hv.w;
        }
    }
    #pragma unroll
    for (int o = 16; o; o >>= 1) {
        dn4.x += __shfl_xor_sync(FULL_M, dn4.x, o);
        dn4.y += __shfl_xor_sync(FULL_M, dn4.y, o);
        dn4.z += __shfl_xor_sync(FULL_M, dn4.z, o);
        dn4.w += __shfl_xor_sync(FULL_M, dn4.w, o);
    }
    float dn = head == 0 ? dn4.x : (head == 1 ? dn4.y : (head == 2 ? dn4.z : dn4.w));
    float inv = 1.f / (dn + EPS_);
    float4 bb = *(const float4*)(b1 + lane * 4);
    float v0 = acc.x * inv + bb.x;
    float v1 = acc.y * inv + bb.y;
    float v2 = acc.z * inv + bb.z;
    float v3 = acc.w * inv + bb.w;
    float4 r;
    r.x = v0 > 0.f ? v0 : expm1f(v0);
    r.y = v1 > 0.f ? v1 : expm1f(v1);
    r.z = v2 > 0.f ? v2 : expm1f(v2);
    r.w = v3 > 0.f ? v3 : expm1f(v3);
    *(float4*)(out + (size_t)w * 128 + lane * 4) = r;
}

// ---------------- layer-2 aggregation (1 head x 128 ch), no max pass ----------------
__global__ void agg2_kernel(const float* __restrict__ h,
                            const float* __restrict__ b2,
                            float* __restrict__ out, int n) {
    int w = (blockIdx.x * blockDim.x + threadIdx.x) >> 5;
    int lane = threadIdx.x & 31;
    if (w >= n) return;
    int beg = g_rowptr[w], end = g_rowptr[w + 1];
    float adn = g_ad2[w];

    float4 acc = make_float4(0.f, 0.f, 0.f, 0.f);
    float dn = 0.f;
    for (int g = beg; g < end; g += 32) {
        int i = g + lane;
        float e = 0.f; int s = 0;
        if (i < end) {
            s = g_csr_src[i];
            e = __expf(lrelu(g_as2[s] + adn));
        }
        dn += e;
        int cnt = min(32, end - g);
        for (int j = 0; j < cnt; j++) {
            float f = __shfl_sync(FULL_M, e, j);
            int  sj = __shfl_sync(FULL_M, s, j);
            float4 hv = *(const float4*)(h + (size_t)sj * 128 + lane * 4);
            acc.x += f * hv.x; acc.y += f * hv.y;
            acc.z += f * hv.z; acc.w += f * hv.w;
        }
    }
    #pragma unroll
    for (int o = 16; o; o >>= 1)
        dn += __shfl_xor_sync(FULL_M, dn, o);
    float inv = 1.f / (dn + EPS_);
    float4 bb = *(const float4*)(b2 + lane * 4);
    float4 r;
    r.x = acc.x * inv + bb.x;
    r.y = acc.y * inv + bb.y;
    r.z = acc.z * inv + bb.z;
    r.w = acc.w * inv + bb.w;
    *(float4*)(out + (size_t)w * 128 + lane * 4) = r;
}

// ---------------- launch ----------------
extern "C" void kernel_launch(void* const* d_in, const int* in_sizes, int n_in,
                              void* d_out, int out_size) {
    const float* x     = (const float*)d_in[0];
    const int*   ei    = (const int*)d_in[1];
    const float* W1    = (const float*)d_in[2];
    const float* asrc1 = (const float*)d_in[3];
    const float* adst1 = (const float*)d_in[4];
    const float* b1    = (const float*)d_in[5];
    const float* W2    = (const float*)d_in[6];
    const float* asrc2 = (const float*)d_in[7];
    const float* adst2 = (const float*)d_in[8];
    const float* b2    = (const float*)d_in[9];
    float* out = (float*)d_out;

    int n = in_sizes[0] / 128;   // 30000
    int E = in_sizes[1] / 2;     // 480000

    float *p_h1, *p_act1, *p_h2;
    cudaGetSymbolAddress((void**)&p_h1,   g_h1);
    cudaGetSymbolAddress((void**)&p_act1, g_act1);
    cudaGetSymbolAddress((void**)&p_h2,   g_h2);

    const int* e_src = ei;
    const int* e_dst = ei + E;

    // graph build (shared by both layers)
    init_kernel<<<(n + 255) / 256, 256>>>(n);
    hist_kernel<<<(E + 1023) / 1024, 256>>>(e_dst, E);
    scan_kernel<<<1, 1024>>>(n);
    scatter_kernel<<<(E + 1023) / 1024, 256>>>(e_src, e_dst, E);

    int ggrid = (n + 127) / 128;
    int warp_blocks = (n * 32 + 255) / 256;

    // layer 1
    gemm128<<<ggrid, 256>>>(x, W1, p_h1, n);
    alpha1_kernel<<<warp_blocks, 256>>>(p_h1, asrc1, adst1, n);
    agg1_kernel<<<warp_blocks, 256>>>(p_h1, b1, p_act1, n);

    // layer 2
    gemm128<<<ggrid, 256>>>(p_act1, W2, p_h2, n);
    alpha2_kernel<<<warp_blocks, 256>>>(p_h2, asrc2, adst2, n);
    agg2_kernel<<<warp_blocks, 256>>>(p_h2, b2, out, n);
}

// round 6
// speedup vs baseline: 1.0906x; 1.0906x over previous
#include <cuda_runtime.h>
#include <math.h>

#define N_MAX   32768
#define EMAX    600000
#define FULL_M  0xffffffffu
#define NEG_SLOPE 0.2f
#define EPS_    1e-16f

// ---------------- device scratch (static: no allocation allowed) ----------------
__device__ int   g_counts[N_MAX];
__device__ int   g_rowptr[N_MAX + 1];
__device__ int   g_edge_off[EMAX];
__device__ int   g_csr_src[EMAX];
__device__ __align__(16) float g_h1[N_MAX * 128];
__device__ __align__(16) float g_act1[N_MAX * 128];
__device__ __align__(16) float g_h2[N_MAX * 128];
__device__ float4 g_as1[N_MAX];
__device__ float4 g_ad1[N_MAX];
__device__ float  g_as2[N_MAX];
__device__ float  g_ad2[N_MAX];

__device__ __forceinline__ float lrelu(float v) { return v > 0.f ? v : NEG_SLOPE * v; }

// ---------------- CSR construction ----------------
__global__ void init_kernel(int n) {
    int i = blockIdx.x * blockDim.x + threadIdx.x;
    if (i < n) g_counts[i] = 1;                       // count=1: implicit self loop
}

// histogram; atomicAdd's return value IS the edge's rank within its bucket
__global__ void hist_kernel(const int* __restrict__ dst, int E) {
    int i = (blockIdx.x * blockDim.x + threadIdx.x) * 4;
    if (i + 3 < E) {
        int4 d = *(const int4*)(dst + i);
        int o0 = atomicAdd(&g_counts[d.x], 1);
        int o1 = atomicAdd(&g_counts[d.y], 1);
        int o2 = atomicAdd(&g_counts[d.z], 1);
        int o3 = atomicAdd(&g_counts[d.w], 1);
        *(int4*)(g_edge_off + i) = make_int4(o0, o1, o2, o3);
    } else {
        for (int j = i; j < E; j++)
            g_edge_off[j] = atomicAdd(&g_counts[dst[j]], 1);
    }
}

// single-block scan: 1024 threads x 32 elems. Writes rowptr and pre-places the
// self loop at slot rowptr[i] (edge ranks from hist start at 1).
__global__ __launch_bounds__(1024) void scan_kernel(int n) {
    __shared__ int wsum[32];
    int tid = threadIdx.x, lane = tid & 31, wid = tid >> 5;
    int base = tid * 32;
    int local[32];
    int sum = 0;
    #pragma unroll
    for (int j = 0; j < 32; j++) {
        int i = base + j;
        local[j] = sum;
        sum += (i < n) ? g_counts[i] : 0;
    }
    int x = sum;
    #pragma unroll
    for (int d = 1; d < 32; d <<= 1) {
        int t = __shfl_up_sync(FULL_M, x, d);
        if (lane >= d) x += t;
    }
    if (lane == 31) wsum[wid] = x;
    __syncthreads();
    if (wid == 0) {
        int y = wsum[lane];
        #pragma unroll
        for (int d = 1; d < 32; d <<= 1) {
            int t = __shfl_up_sync(FULL_M, y, d);
            if (lane >= d) y += t;
        }
        wsum[lane] = y;
    }
    __syncthreads();
    int offset = (x - sum) + (wid > 0 ? wsum[wid - 1] : 0);
    if (tid == 0) g_rowptr[0] = 0;
    #pragma unroll
    for (int j = 0; j < 32; j++) {
        int i = base + j;
        if (i < n) {
            int c = g_counts[i];
            int start = offset + local[j];
            g_rowptr[i + 1] = start + c;
            g_csr_src[start] = i;                     // self loop first
        }
    }
}

// atomic-free scatter: pos = rowptr[dst] + precomputed rank
__global__ void scatter_kernel(const int* __restrict__ src,
                               const int* __restrict__ dst, int E) {
    int i = (blockIdx.x * blockDim.x + threadIdx.x) * 4;
    if (i + 3 < E) {
        int4 s = *(const int4*)(src + i);
        int4 d = *(const int4*)(dst + i);
        int4 o = *(const int4*)(g_edge_off + i);
        g_csr_src[g_rowptr[d.x] + o.x] = s.x;
        g_csr_src[g_rowptr[d.y] + o.y] = s.y;
        g_csr_src[g_rowptr[d.z] + o.z] = s.z;
        g_csr_src[g_rowptr[d.w] + o.w] = s.w;
    } else {
        for (int j = i; j < E; j++)
            g_csr_src[g_rowptr[dst[j]] + g_edge_off[j]] = src[j];
    }
}

// ---------------- GEMM: C[M,128] = A[M,128] * B[128,128], fp32 (R3 proven) ----------------
__global__ void gemm128(const float* __restrict__ A, const float* __restrict__ B,
                        float* __restrict__ C, int M) {
    __shared__ __align__(16) float As[64][36];
    __shared__ __align__(16) float Bs[32][68];
    int tid = threadIdx.x, tx = tid & 15, ty = tid >> 4;
    int m0 = blockIdx.x * 64, n0 = blockIdx.y * 64;
    float acc[4][4] = {};
    for (int kk = 0; kk < 4; kk++) {
        int k0 = kk * 32;
        #pragma unroll
        for (int j = 0; j < 2; j++) {
            int idx = tid + j * 256;
            int r = idx >> 3, k4 = idx & 7;
            float4 v = make_float4(0.f, 0.f, 0.f, 0.f);
            int row = m0 + r;
            if (row < M) v = *(const float4*)(A + row * 128 + k0 + k4 * 4);
            *(float4*)&As[r][k4 * 4] = v;
        }
        #pragma unroll
        for (int j = 0; j < 2; j++) {
            int idx = tid + j * 256;
            int k = idx >> 4, c4 = idx & 15;
            float4 v = *(const float4*)(B + (k0 + k) * 128 + n0 + c4 * 4);
            *(float4*)&Bs[k][c4 * 4] = v;
        }
        __syncthreads();
        #pragma unroll
        for (int k = 0; k < 32; k++) {
            float4 b = *(const float4*)&Bs[k][tx * 4];
            #pragma unroll
            for (int i = 0; i < 4; i++) {
                float a = As[ty * 4 + i][k];
                acc[i][0] += a * b.x; acc[i][1] += a * b.y;
                acc[i][2] += a * b.z; acc[i][3] += a * b.w;
            }
        }
        __syncthreads();
    }
    #pragma unroll
    for (int i = 0; i < 4; i++) {
        int row = m0 + ty * 4 + i;
        if (row < M)
            *(float4*)(C + row * 128 + n0 + tx * 4) =
                make_float4(acc[i][0], acc[i][1], acc[i][2], acc[i][3]);
    }
}

// ---------------- per-node attention coefficients ----------------
__global__ void alpha1_kernel(const float* __restrict__ h,
                              const float* __restrict__ a_src,
                              const float* __restrict__ a_dst, int n) {
    int w = (blockIdx.x * blockDim.x + threadIdx.x) >> 5;
    int lane = threadIdx.x & 31;
    if (w >= n) return;
    float4 hv = *(const float4*)(h + (size_t)w * 128 + lane * 4);
    float4 av = *(const float4*)(a_src + lane * 4);
    float4 dv = *(const float4*)(a_dst + lane * 4);
    float ps = hv.x * av.x + hv.y * av.y + hv.z * av.z + hv.w * av.w;
    float pd = hv.x * dv.x + hv.y * dv.y + hv.z * dv.z + hv.w * dv.w;
    #pragma unroll
    for (int o = 4; o; o >>= 1) {        // reduce within 8-lane head groups
        ps += __shfl_xor_sync(FULL_M, ps, o);
        pd += __shfl_xor_sync(FULL_M, pd, o);
    }
    float s0 = __shfl_sync(FULL_M, ps, 0),  s1 = __shfl_sync(FULL_M, ps, 8);
    float s2 = __shfl_sync(FULL_M, ps, 16), s3 = __shfl_sync(FULL_M, ps, 24);
    float d0 = __shfl_sync(FULL_M, pd, 0),  d1 = __shfl_sync(FULL_M, pd, 8);
    float d2 = __shfl_sync(FULL_M, pd, 16), d3 = __shfl_sync(FULL_M, pd, 24);
    if (lane == 0) {
        g_as1[w] = make_float4(s0, s1, s2, s3);
        g_ad1[w] = make_float4(d0, d1, d2, d3);
    }
}

__global__ void alpha2_kernel(const float* __restrict__ h,
                              const float* __restrict__ a_src,
                              const float* __restrict__ a_dst, int n) {
    int w = (blockIdx.x * blockDim.x + threadIdx.x) >> 5;
    int lane = threadIdx.x & 31;
    if (w >= n) return;
    float4 hv = *(const float4*)(h + (size_t)w * 128 + lane * 4);
    float4 av = *(const float4*)(a_src + lane * 4);
    float4 dv = *(const float4*)(a_dst + lane * 4);
    float s = hv.x * av.x + hv.y * av.y + hv.z * av.z + hv.w * av.w;
    float d = hv.x * dv.x + hv.y * dv.y + hv.z * dv.z + hv.w * dv.w;
    #pragma unroll
    for (int o = 16; o; o >>= 1) {
        s += __shfl_xor_sync(FULL_M, s, o);
        d += __shfl_xor_sync(FULL_M, d, o);
    }
    if (lane == 0) { g_as2[w] = s; g_ad2[w] = d; }
}

// ---------------- layer-1 aggregation (4 heads x 32 ch): no max pass,
// float4 gathers, fully-unrolled predicated inner loop (8-edge groups) -----------
__global__ void agg1_kernel(const float* __restrict__ h,
                            const float* __restrict__ b1,
                            float* __restrict__ out, int n) {
    int w = (blockIdx.x * blockDim.x + threadIdx.x) >> 5;
    int lane = threadIdx.x & 31;
    if (w >= n) return;
    int beg = g_rowptr[w], end = g_rowptr[w + 1];
    float4 ad = g_ad1[w];
    int head = lane >> 3;   // channels [4*lane, 4*lane+4) all live in head lane>>3

    float4 acc = make_float4(0.f, 0.f, 0.f, 0.f);
    float4 dn4 = make_float4(0.f, 0.f, 0.f, 0.f);
    for (int gb = beg; gb < end; gb += 32) {
        int i = gb + lane;
        float4 e4 = make_float4(0.f, 0.f, 0.f, 0.f);
        int s = 0;
        if (i < end) {
            s = g_csr_src[i];
            float4 a = g_as1[s];
            e4.x = __expf(lrelu(a.x + ad.x));
            e4.y = __expf(lrelu(a.y + ad.y));
            e4.z = __expf(lrelu(a.z + ad.z));
            e4.w = __expf(lrelu(a.w + ad.w));
        }
        dn4.x += e4.x; dn4.y += e4.y; dn4.z += e4.z; dn4.w += e4.w;
        #pragma unroll
        for (int j0 = 0; j0 < 32; j0 += 8) {
            if (gb + j0 >= end) break;       // skip fully-empty 8-edge groups
            #pragma unroll
            for (int j = j0; j < j0 + 8; j++) {
                float f0 = __shfl_sync(FULL_M, e4.x, j);
                float f1 = __shfl_sync(FULL_M, e4.y, j);
                float f2 = __shfl_sync(FULL_M, e4.z, j);
                float f3 = __shfl_sync(FULL_M, e4.w, j);
                int  sj = __shfl_sync(FULL_M, s, j);
                float f = head == 0 ? f0 : (head == 1 ? f1 : (head == 2 ? f2 : f3));
                if (f > 0.f) {
                    float4 hv = *(const float4*)(h + (size_t)sj * 128 + lane * 4);
                    acc.x += f * hv.x; acc.y += f * hv.y;
                    acc.z += f * hv.z; acc.w += f * hv.w;
                }
            }
        }
    }
    #pragma unroll
    for (int o = 16; o; o >>= 1) {
        dn4.x += __shfl_xor_sync(FULL_M, dn4.x, o);
        dn4.y += __shfl_xor_sync(FULL_M, dn4.y, o);
        dn4.z += __shfl_xor_sync(FULL_M, dn4.z, o);
        dn4.w += __shfl_xor_sync(FULL_M, dn4.w, o);
    }
    float dn = head == 0 ? dn4.x : (head == 1 ? dn4.y : (head == 2 ? dn4.z : dn4.w));
    float inv = 1.f / (dn + EPS_);
    float4 bb = *(const float4*)(b1 + lane * 4);
    float v0 = acc.x * inv + bb.x;
    float v1 = acc.y * inv + bb.y;
    float v2 = acc.z * inv + bb.z;
    float v3 = acc.w * inv + bb.w;
    float4 r;
    r.x = v0 > 0.f ? v0 : expm1f(v0);   // ELU(alpha=1)
    r.y = v1 > 0.f ? v1 : expm1f(v1);
    r.z = v2 > 0.f ? v2 : expm1f(v2);
    r.w = v3 > 0.f ? v3 : expm1f(v3);
    *(float4*)(out + (size_t)w * 128 + lane * 4) = r;
}

// ---------------- layer-2 aggregation (1 head x 128 ch): no max pass ----------------
__global__ void agg2_kernel(const float* __restrict__ h,
                            const float* __restrict__ b2,
                            float* __restrict__ out, int n) {
    int w = (blockIdx.x * blockDim.x + threadIdx.x) >> 5;
    int lane = threadIdx.x & 31;
    if (w >= n) return;
    int beg = g_rowptr[w], end = g_rowptr[w + 1];
    float adn = g_ad2[w];

    float4 acc = make_float4(0.f, 0.f, 0.f, 0.f);
    float dn = 0.f;
    for (int gb = beg; gb < end; gb += 32) {
        int i = gb + lane;
        float e = 0.f; int s = 0;
        if (i < end) {
            s = g_csr_src[i];
            e = __expf(lrelu(g_as2[s] + adn));
        }
        dn += e;
        #pragma unroll
        for (int j0 = 0; j0 < 32; j0 += 8) {
            if (gb + j0 >= end) break;
            #pragma unroll
            for (int j = j0; j < j0 + 8; j++) {
                float f = __shfl_sync(FULL_M, e, j);
                int  sj = __shfl_sync(FULL_M, s, j);
                if (f > 0.f) {
                    float4 hv = *(const float4*)(h + (size_t)sj * 128 + lane * 4);
                    acc.x += f * hv.x; acc.y += f * hv.y;
                    acc.z += f * hv.z; acc.w += f * hv.w;
                }
            }
        }
    }
    #pragma unroll
    for (int o = 16; o; o >>= 1)
        dn += __shfl_xor_sync(FULL_M, dn, o);
    float inv = 1.f / (dn + EPS_);
    float4 bb = *(const float4*)(b2 + lane * 4);
    float4 r;
    r.x = acc.x * inv + bb.x;
    r.y = acc.y * inv + bb.y;
    r.z = acc.z * inv + bb.z;
    r.w = acc.w * inv + bb.w;
    *(float4*)(out + (size_t)w * 128 + lane * 4) = r;
}

// ---------------- launch ----------------
extern "C" void kernel_launch(void* const* d_in, const int* in_sizes, int n_in,
                              void* d_out, int out_size) {
    const float* x     = (const float*)d_in[0];
    const int*   ei    = (const int*)d_in[1];
    const float* W1    = (const float*)d_in[2];
    const float* asrc1 = (const float*)d_in[3];
    const float* adst1 = (const float*)d_in[4];
    const float* b1    = (const float*)d_in[5];
    const float* W2    = (const float*)d_in[6];
    const float* asrc2 = (const float*)d_in[7];
    const float* adst2 = (const float*)d_in[8];
    const float* b2    = (const float*)d_in[9];
    float* out = (float*)d_out;

    int n = in_sizes[0] / 128;   // 30000
    int E = in_sizes[1] / 2;     // 480000

    float *p_h1, *p_act1, *p_h2;
    cudaGetSymbolAddress((void**)&p_h1,   g_h1);
    cudaGetSymbolAddress((void**)&p_act1, g_act1);
    cudaGetSymbolAddress((void**)&p_h2,   g_h2);

    const int* e_src = ei;
    const int* e_dst = ei + E;

    // graph build (shared by both layers)
    init_kernel<<<(n + 255) / 256, 256>>>(n);
    hist_kernel<<<(E + 1023) / 1024, 256>>>(e_dst, E);
    scan_kernel<<<1, 1024>>>(n);
    scatter_kernel<<<(E + 1023) / 1024, 256>>>(e_src, e_dst, E);

    dim3 ggrid((n + 63) / 64, 2);
    int warp_blocks = (n * 32 + 255) / 256;

    // layer 1
    gemm128<<<ggrid, 256>>>(x, W1, p_h1, n);
    alpha1_kernel<<<warp_blocks, 256>>>(p_h1, asrc1, adst1, n);
    agg1_kernel<<<warp_blocks, 256>>>(p_h1, b1, p_act1, n);

    // layer 2
    gemm128<<<ggrid, 256>>>(p_act1, W2, p_h2, n);
    alpha2_kernel<<<warp_blocks, 256>>>(p_h2, asrc2, adst2, n);
    agg2_kernel<<<warp_blocks, 256>>>(p_h2, b2, out, n);
}